// round 13
// baseline (speedup 1.0000x reference)
#include <cuda_runtime.h>

#define D    32
#define KN   26
#define CPW  4               // cells per warp (2 pairs)
#define WPB  12
#define TPB  (WPB * 32)
#define NMAX 125000
#define XSTR 36
#define MASK26 0x3ffffffu

__device__ float g_msg[NMAX * D];

__device__ __forceinline__ float tanh_fast(float x) {
    float y;
    asm("tanh.approx.f32 %0, %1;" : "=f"(y) : "f"(x));
    return y;
}

// ---------------------------------------------------------------------------
// Prepass: g_msg[cell] = tanh(states[cell] @ W_msg + b_msg)
// ---------------------------------------------------------------------------
__global__ __launch_bounds__(384) void msg_prepass(
    int n, const float* __restrict__ states,
    const float* __restrict__ W_msg, const float* __restrict__ b_msg)
{
    __shared__ float sx[12][4 * XSTR];
    const int lane = threadIdx.x & 31, warp = threadIdx.x >> 5;
    const int base = (blockIdx.x * 12 + warp) * 4;
    if (base >= n) return;

    float wm[D];
#pragma unroll
    for (int i = 0; i < D; i++) wm[i] = __ldg(W_msg + i * D + lane);
    const float bm = __ldg(b_msg + lane);

    float* xb = sx[warp];
#pragma unroll
    for (int c = 0; c < 4; c++) {
        int cell = base + c;
        xb[c * XSTR + lane] = (cell < n) ? states[cell * D + lane] : 0.f;
    }
    __syncwarp();
#pragma unroll
    for (int c = 0; c < 4; c++) {
        int cell = base + c;
        float m = bm;
#pragma unroll
        for (int i8 = 0; i8 < 8; i8++) {
            float4 xv = *reinterpret_cast<const float4*>(xb + c * XSTR + 4 * i8);
            m = fmaf(xv.x, wm[4 * i8 + 0], m);
            m = fmaf(xv.y, wm[4 * i8 + 1], m);
            m = fmaf(xv.z, wm[4 * i8 + 2], m);
            m = fmaf(xv.w, wm[4 * i8 + 3], m);
        }
        if (cell < n) g_msg[cell * D + lane] = tanh_fast(m);
    }
}

// ---------------------------------------------------------------------------
// Main: cell-pair-per-warp gather (halves own distinct cells), 48 warps/SM
// ---------------------------------------------------------------------------
__global__ __launch_bounds__(TPB, 4) void moe_main(
    int n,
    const float* __restrict__ states,
    const int*   __restrict__ nbr,
    const int*   __restrict__ tiers,
    const float* __restrict__ W_loc,  const float* __restrict__ b_loc,
    const float* __restrict__ W_fun,  const float* __restrict__ b_fun,
    const float* __restrict__ W_cnf,  const float* __restrict__ b_cnf,
    const float* __restrict__ W_gate, const float* __restrict__ b_gate,
    float* __restrict__ out)
{
    extern __shared__ char smem[];
    float4* sWloc4 = reinterpret_cast<float4*>(smem);
    float4* sWfun4 = sWloc4 + 16 * 32;
    float4* sWcnf4 = sWfun4 + 16 * 32;
    float4* sInAll = sWcnf4 + 16 * 32;           // WPB*CPW*32 float4
    float4* sGate  = sInAll + WPB * CPW * D;     // WPB*CPW

    for (int e = threadIdx.x; e < 16 * 32; e += TPB) {
        int i = (e >> 5) * 4, j = e & 31;
        sWloc4[e] = make_float4(W_loc[i * 32 + j], W_loc[(i + 1) * 32 + j],
                                W_loc[(i + 2) * 32 + j], W_loc[(i + 3) * 32 + j]);
        sWfun4[e] = make_float4(W_fun[i * 32 + j], W_fun[(i + 1) * 32 + j],
                                W_fun[(i + 2) * 32 + j], W_fun[(i + 3) * 32 + j]);
        sWcnf4[e] = make_float4(W_cnf[i * 32 + j], W_cnf[(i + 1) * 32 + j],
                                W_cnf[(i + 2) * 32 + j], W_cnf[(i + 3) * 32 + j]);
    }
    __syncthreads();

    const int lane = threadIdx.x & 31, warp = threadIdx.x >> 5;
    const int base = (blockIdx.x * WPB + warp) * CPW;
    if (base >= n) return;
    const unsigned FULL = 0xffffffffu;

    const bool hiHalf = (lane >> 4) != 0;
    const int  sub8   = (lane & 15) * 8;
    const char* sbase = (const char*)states;
    const char* mbase = (const char*)g_msg;

    float4* inb = sInAll + warp * (CPW * D);
    float4* gwp = sGate  + warp * CPW;

    float wg[4][3];
#pragma unroll
    for (int s = 0; s < 4; s++)
#pragma unroll
        for (int e = 0; e < 3; e++)
            wg[s][e] = __ldg(W_gate + (s * D + lane) * 3 + e);
    const float bg0 = __ldg(b_gate + 0), bg1 = __ldg(b_gate + 1), bg2 = __ldg(b_gate + 2);

    const int lnk = min(lane, KN - 1);

    // ---- gather: two cells per warp (one per half), 26 LDG.64 per pair ----
#pragma unroll
    for (int p = 0; p < CPW / 2; p++) {
        const int cA = min(base + 2 * p,     n - 1);
        const int cB = min(base + 2 * p + 1, n - 1);

        const float cuA = states[cA * D + lane];
        const float cuB = states[cB * D + lane];

        const int pkA = __ldg(nbr + cA * KN + lnk) * 128 + __ldg(tiers + cA * KN + lnk);
        const int pkB = __ldg(nbr + cB * KN + lnk) * 128 + __ldg(tiers + cB * KN + lnk);

        const int tAl = pkA & 3, tBl = pkB & 3;
        const unsigned m0A = __ballot_sync(FULL, tAl == 0) & MASK26;
        const unsigned m1A = __ballot_sync(FULL, tAl == 1) & MASK26;
        const unsigned m0B = __ballot_sync(FULL, tBl == 0) & MASK26;
        const unsigned m1B = __ballot_sync(FULL, tBl == 1) & MASK26;
        const int n0A = __popc(m0A), n1A = __popc(m1A);
        const int n0B = __popc(m0B), n1B = __popc(m1B);

        // per-lane packed accumulators: half 0 lanes -> cell A, half 1 -> cell B
        unsigned long long t2 = 0ull, a02 = 0ull, s012 = 0ull, fm2 = 0ull;
#pragma unroll
        for (int j = 0; j < KN; j++) {
            const int pA = __shfl_sync(FULL, pkA, j);
            const int pB = __shfl_sync(FULL, pkB, j);
            const int pk = hiHalf ? pB : pA;
            const int t  = pk & 3;
            const long off = (long)(pk & ~127) + sub8;

            // state row: 16 lanes x 8B = full 128B row per half (C load: batchable)
            const float2 v2 = __ldcg(reinterpret_cast<const float2*>(sbase + off));
            unsigned long long v;
            asm("mov.b64 %0, {%1, %2};" : "=l"(v) : "f"(v2.x), "f"(v2.y));

            asm("add.rn.f32x2 %0, %0, %1;" : "+l"(t2) : "l"(v));
            asm("{.reg .pred p; setp.eq.s32 p, %2, 0; @p add.rn.f32x2 %0, %0, %1;}"
                : "+l"(a02) : "l"(v), "r"(t));
            asm("{.reg .pred p; setp.le.s32 p, %2, 1; @p add.rn.f32x2 %0, %0, %1;}"
                : "+l"(s012) : "l"(v), "r"(t));

            unsigned long long mv;
            asm("{.reg .pred p; setp.eq.s32 p, %2, 1; mov.b64 %0, 0; @p ld.global.cg.b64 %0, [%1];}"
                : "=l"(mv) : "l"(mbase + off), "r"(t));
            asm("add.rn.f32x2 %0, %0, %1;" : "+l"(fm2) : "l"(mv));
        }

        // unpack
        float tl, th, a0l, a0h, sl, sh, fml, fmh;
        asm("mov.b64 {%0,%1}, %2;" : "=f"(tl),  "=f"(th)  : "l"(t2));
        asm("mov.b64 {%0,%1}, %2;" : "=f"(a0l), "=f"(a0h) : "l"(a02));
        asm("mov.b64 {%0,%1}, %2;" : "=f"(sl),  "=f"(sh)  : "l"(sl=0, s012));
        asm("mov.b64 {%0,%1}, %2;" : "=f"(fml), "=f"(fmh) : "l"(fm2));

        // redistribute: for cell q, dim d lives in lane q*16 + (d>>1), comp d&1
        const bool odd = (lane & 1);
#pragma unroll
        for (int q = 0; q < 2; q++) {
            const int src = q * 16 + (lane >> 1);
            const float tLo = __shfl_sync(FULL, tl,  src), tHi = __shfl_sync(FULL, th,  src);
            const float aLo = __shfl_sync(FULL, a0l, src), aHi = __shfl_sync(FULL, a0h, src);
            const float sLo = __shfl_sync(FULL, sl,  src), sHi = __shfl_sync(FULL, sh,  src);
            const float fLo = __shfl_sync(FULL, fml, src), fHi = __shfl_sync(FULL, fmh, src);
            const float tot = odd ? tHi : tLo;
            const float a0s = odd ? aHi : aLo;
            const float s01 = odd ? sHi : sLo;
            const float fms = odd ? fHi : fLo;

            const int nn0 = q ? n0B : n0A;
            const int nn1 = q ? n1B : n1A;
            const int nn2 = KN - nn0 - nn1;
            const float cu = q ? cuB : cuA;

            const float a0 = __fdividef(a0s,       fmaxf((float)nn0, 1.f));
            const float a1 = __fdividef(s01 - a0s, fmaxf((float)nn1, 1.f));
            const float a2 = __fdividef(tot - s01, fmaxf((float)nn2, 1.f));
            const float fm = __fdividef(fms,       fmaxf((float)nn1, 1.f));

            inb[(2 * p + q) * D + lane] = make_float4(cu, a0, fm, a2);

            float p0 = cu * wg[0][0] + a0 * wg[1][0] + a1 * wg[2][0] + a2 * wg[3][0];
            float p1 = cu * wg[0][1] + a0 * wg[1][1] + a1 * wg[2][1] + a2 * wg[3][1];
            float p2 = cu * wg[0][2] + a0 * wg[1][2] + a1 * wg[2][2] + a2 * wg[3][2];
#pragma unroll
            for (int o = 16; o > 0; o >>= 1) {
                p0 += __shfl_xor_sync(FULL, p0, o);
                p1 += __shfl_xor_sync(FULL, p1, o);
                p2 += __shfl_xor_sync(FULL, p2, o);
            }
            if (lane == 0) {
                const float g0 = p0 + bg0, g1 = p1 + bg1, g2 = p2 + bg2;
                const float mx = fmaxf(g0, fmaxf(g1, g2));
                const float e0 = __expf(g0 - mx), e1 = __expf(g1 - mx), e2 = __expf(g2 - mx);
                const float inv = __fdividef(1.f, e0 + e1 + e2);
                gwp[2 * p + q] = make_float4(e0 * inv, e1 * inv, e2 * inv, 0.f);
            }
        }
    }
    __syncwarp();

    // ---- fused pass: loc, fun, CNF conditioning half (h2) ----
    float accL[CPW], accF[CPW], h2[CPW];
    {
        const float bl = __ldg(b_loc + lane);
        const float bf = __ldg(b_fun + lane);
        const float bc = __ldg(b_cnf + lane);
#pragma unroll
        for (int c = 0; c < CPW; c++) { accL[c] = bl; accF[c] = bf; h2[c] = bc; }
    }

#pragma unroll
    for (int i4 = 0; i4 < 8; i4++) {
        const float4 wlT = sWloc4[i4 * 32 + lane];
        const float4 wlB = sWloc4[(i4 + 8) * 32 + lane];
        const float4 wfT = sWfun4[i4 * 32 + lane];
        const float4 wfB = sWfun4[(i4 + 8) * 32 + lane];
        const float4 wcB = sWcnf4[(i4 + 8) * 32 + lane];
#pragma unroll
        for (int c = 0; c < CPW; c++) {
            const float4 x0 = inb[c * D + 4 * i4 + 0];
            const float4 x1 = inb[c * D + 4 * i4 + 1];
            const float4 x2 = inb[c * D + 4 * i4 + 2];
            const float4 x3 = inb[c * D + 4 * i4 + 3];
            accL[c] = fmaf(x0.x, wlT.x, fmaf(x0.y, wlB.x, accL[c]));
            accL[c] = fmaf(x1.x, wlT.y, fmaf(x1.y, wlB.y, accL[c]));
            accL[c] = fmaf(x2.x, wlT.z, fmaf(x2.y, wlB.z, accL[c]));
            accL[c] = fmaf(x3.x, wlT.w, fmaf(x3.y, wlB.w, accL[c]));
            accF[c] = fmaf(x0.x, wfT.x, fmaf(x0.z, wfB.x, accF[c]));
            accF[c] = fmaf(x1.x, wfT.y, fmaf(x1.z, wfB.y, accF[c]));
            accF[c] = fmaf(x2.x, wfT.z, fmaf(x2.z, wfB.z, accF[c]));
            accF[c] = fmaf(x3.x, wfT.w, fmaf(x3.z, wfB.w, accF[c]));
            h2[c]   = fmaf(x0.w, wcB.x, h2[c]);
            h2[c]   = fmaf(x1.w, wcB.y, h2[c]);
            h2[c]   = fmaf(x2.w, wcB.z, h2[c]);
            h2[c]   = fmaf(x3.w, wcB.w, h2[c]);
        }
    }

    // ---- partial combine, init CNF state ----
    float opart[CPW], gw2[CPW], x[CPW];
#pragma unroll
    for (int c = 0; c < CPW; c++) {
        const float4 gwv = gwp[c];
        opart[c] = gwv.x * tanh_fast(accL[c]) + gwv.y * tanh_fast(accF[c]);
        gw2[c]   = gwv.z;
        x[c]     = inb[c * D + lane].x;
    }
    __syncwarp();

    // ---- CNF: 3 Euler steps; x staged into the now-dead sIn region ----
    float* xxb = reinterpret_cast<float*>(inb);
#pragma unroll
    for (int s = 0; s < 3; s++) {
        __syncwarp();
#pragma unroll
        for (int c = 0; c < CPW; c++) xxb[c * XSTR + lane] = x[c];
        __syncwarp();
        float acc[CPW];
#pragma unroll
        for (int c = 0; c < CPW; c++) acc[c] = h2[c];
#pragma unroll
        for (int i4 = 0; i4 < 8; i4++) {
            const float4 w = sWcnf4[i4 * 32 + lane];
#pragma unroll
            for (int c = 0; c < CPW; c++) {
                const float4 xv = *reinterpret_cast<const float4*>(xxb + c * XSTR + 4 * i4);
                acc[c] = fmaf(xv.x, w.x, fmaf(xv.y, w.y, fmaf(xv.z, w.z, fmaf(xv.w, w.w, acc[c]))));
            }
        }
#pragma unroll
        for (int c = 0; c < CPW; c++)
            x[c] = fmaf(1.0f / 3.0f, tanh_fast(acc[c]), x[c]);
    }

    // ---- final combine + store ----
#pragma unroll
    for (int c = 0; c < CPW; c++) {
        const int cell = base + c;
        if (cell < n)
            out[cell * D + lane] = opart[c] + gw2[c] * x[c];
    }
}

extern "C" void kernel_launch(void* const* d_in, const int* in_sizes, int n_in,
                              void* d_out, int out_size) {
    const float* states = (const float*)d_in[0];
    const int*   nbr    = (const int*)  d_in[1];
    const int*   tiers  = (const int*)  d_in[2];
    const float* W_loc  = (const float*)d_in[3];
    const float* b_loc  = (const float*)d_in[4];
    const float* W_msg  = (const float*)d_in[5];
    const float* b_msg  = (const float*)d_in[6];
    const float* W_fun  = (const float*)d_in[7];
    const float* b_fun  = (const float*)d_in[8];
    const float* W_cnf  = (const float*)d_in[9];
    const float* b_cnf  = (const float*)d_in[10];
    const float* W_gate = (const float*)d_in[11];
    const float* b_gate = (const float*)d_in[12];
    float* out = (float*)d_out;

    const int n = in_sizes[0] / D;
    const int blocksP = (n + 12 * 4 - 1) / (12 * 4);
    const int blocks  = (n + WPB * CPW - 1) / (WPB * CPW);

    const int smem_bytes = (3 * 16 * 32) * (int)sizeof(float4)
                         + (WPB * CPW * D) * (int)sizeof(float4)
                         + (WPB * CPW) * (int)sizeof(float4);
    static bool attr_set = false;
    if (!attr_set) {
        cudaFuncSetAttribute(moe_main, cudaFuncAttributeMaxDynamicSharedMemorySize, smem_bytes);
        attr_set = true;
    }

    msg_prepass<<<blocksP, 384>>>(n, states, W_msg, b_msg);
    moe_main<<<blocks, TPB, smem_bytes>>>(n, states, nbr, tiers,
                                          W_loc, b_loc, W_fun, b_fun,
                                          W_cnf, b_cnf, W_gate, b_gate, out);
}

// round 14
// speedup vs baseline: 1.1937x; 1.1937x over previous
#include <cuda_runtime.h>

#define D    32
#define KN   26
#define CPW  4
#define WPB  12
#define TPB  (WPB * 32)
#define NMAX 125000
#define XSTR 36
#define MASK26 0x3ffffffu

__device__ float g_msg[NMAX * D];

__device__ __forceinline__ float tanh_fast(float x) {
    float y;
    asm("tanh.approx.f32 %0, %1;" : "=f"(y) : "f"(x));
    return y;
}

// ---------------------------------------------------------------------------
// Prepass: g_msg[cell] = tanh(states[cell] @ W_msg + b_msg)
// ---------------------------------------------------------------------------
__global__ __launch_bounds__(384) void msg_prepass(
    int n, const float* __restrict__ states,
    const float* __restrict__ W_msg, const float* __restrict__ b_msg)
{
    __shared__ float sx[12][4 * XSTR];
    const int lane = threadIdx.x & 31, warp = threadIdx.x >> 5;
    const int base = (blockIdx.x * 12 + warp) * 4;
    if (base >= n) return;

    float wm[D];
#pragma unroll
    for (int i = 0; i < D; i++) wm[i] = __ldg(W_msg + i * D + lane);
    const float bm = __ldg(b_msg + lane);

    float* xb = sx[warp];
#pragma unroll
    for (int c = 0; c < 4; c++) {
        int cell = base + c;
        xb[c * XSTR + lane] = (cell < n) ? states[cell * D + lane] : 0.f;
    }
    __syncwarp();
#pragma unroll
    for (int c = 0; c < 4; c++) {
        int cell = base + c;
        float m = bm;
#pragma unroll
        for (int i8 = 0; i8 < 8; i8++) {
            float4 xv = *reinterpret_cast<const float4*>(xb + c * XSTR + 4 * i8);
            m = fmaf(xv.x, wm[4 * i8 + 0], m);
            m = fmaf(xv.y, wm[4 * i8 + 1], m);
            m = fmaf(xv.z, wm[4 * i8 + 2], m);
            m = fmaf(xv.w, wm[4 * i8 + 3], m);
        }
        if (cell < n) g_msg[cell * D + lane] = tanh_fast(m);
    }
}

// ---------------------------------------------------------------------------
// Main: scalar gather with EXPLICIT 13-wide load batches (forced high MLP)
// ---------------------------------------------------------------------------
__global__ __launch_bounds__(TPB, 3) void moe_main(
    int n,
    const float* __restrict__ states,
    const int*   __restrict__ nbr,
    const int*   __restrict__ tiers,
    const float* __restrict__ W_loc,  const float* __restrict__ b_loc,
    const float* __restrict__ W_fun,  const float* __restrict__ b_fun,
    const float* __restrict__ W_cnf,  const float* __restrict__ b_cnf,
    const float* __restrict__ W_gate, const float* __restrict__ b_gate,
    float* __restrict__ out)
{
    extern __shared__ char smem[];
    float4* sWloc4 = reinterpret_cast<float4*>(smem);
    float4* sWfun4 = sWloc4 + 16 * 32;
    float4* sWcnf4 = sWfun4 + 16 * 32;
    float4* sInAll = sWcnf4 + 16 * 32;           // WPB*CPW*32 float4
    float4* sGate  = sInAll + WPB * CPW * D;     // WPB*CPW

    for (int e = threadIdx.x; e < 16 * 32; e += TPB) {
        int i = (e >> 5) * 4, j = e & 31;
        sWloc4[e] = make_float4(W_loc[i * 32 + j], W_loc[(i + 1) * 32 + j],
                                W_loc[(i + 2) * 32 + j], W_loc[(i + 3) * 32 + j]);
        sWfun4[e] = make_float4(W_fun[i * 32 + j], W_fun[(i + 1) * 32 + j],
                                W_fun[(i + 2) * 32 + j], W_fun[(i + 3) * 32 + j]);
        sWcnf4[e] = make_float4(W_cnf[i * 32 + j], W_cnf[(i + 1) * 32 + j],
                                W_cnf[(i + 2) * 32 + j], W_cnf[(i + 3) * 32 + j]);
    }
    __syncthreads();

    const int lane = threadIdx.x & 31, warp = threadIdx.x >> 5;
    const int base = (blockIdx.x * WPB + warp) * CPW;
    if (base >= n) return;
    const unsigned FULL = 0xffffffffu;

    const char* sb = (const char*)states + lane * 4;
    const char* mb = (const char*)g_msg  + lane * 4;

    float4* inb = sInAll + warp * (CPW * D);
    float4* gwp = sGate  + warp * CPW;

    float wg[4][3];
#pragma unroll
    for (int s = 0; s < 4; s++)
#pragma unroll
        for (int e = 0; e < 3; e++)
            wg[s][e] = __ldg(W_gate + (s * D + lane) * 3 + e);
    const float bg0 = __ldg(b_gate + 0), bg1 = __ldg(b_gate + 1), bg2 = __ldg(b_gate + 2);

    const int lnk = min(lane, KN - 1);

    // ---- gather: 2 x (13-load batch -> accumulate) + eager gate ----
#pragma unroll
    for (int c = 0; c < CPW; c++) {
        const int cellc = min(base + c, n - 1);

        const float cu = states[cellc * D + lane];
        const int idx  = __ldg(nbr   + cellc * KN + lnk);
        const int myt  = __ldg(tiers + cellc * KN + lnk);
        const int mypk = idx * 128 + myt;

        const unsigned m0 = __ballot_sync(FULL, myt == 0) & MASK26;
        const unsigned m1 = __ballot_sync(FULL, myt == 1) & MASK26;
        const int n0 = __popc(m0), n1 = __popc(m1);
        const int n2 = KN - n0 - n1;

        float tot = 0.f, a0s = 0.f, s01 = 0.f, fm = 0.f;

#pragma unroll
        for (int h = 0; h < 2; h++) {
            // --- load batch: 13 independent plain loads (forced MLP) ---
            float v[13];
#pragma unroll
            for (int j = 0; j < 13; j++) {
                const int pk = __shfl_sync(FULL, mypk, h * 13 + j);
                v[j] = __ldcg((const float*)(sb + (long)(pk & ~127)));
            }
            // --- accumulate + independent msg loads ---
#pragma unroll
            for (int j = 0; j < 13; j++) {
                const int pk = __shfl_sync(FULL, mypk, h * 13 + j);
                const int t  = pk & 3;
                float mv;
                asm("{.reg .pred p; setp.eq.s32 p, %2, 1; mov.f32 %0, 0f00000000;"
                    " @p ld.global.cg.f32 %0, [%1];}"
                    : "=f"(mv) : "l"(mb + (long)(pk & ~127)), "r"(t));
                tot += v[j];
                a0s += (t == 0) ? v[j] : 0.f;
                s01 += (t <= 1) ? v[j] : 0.f;
                fm  += mv;
            }
        }

        const float a0 = __fdividef(a0s,       fmaxf((float)n0, 1.f));
        const float a1 = __fdividef(s01 - a0s, fmaxf((float)n1, 1.f));
        const float a2 = __fdividef(tot - s01, fmaxf((float)n2, 1.f));
        const float fmn = __fdividef(fm,       fmaxf((float)n1, 1.f));

        inb[c * D + lane] = make_float4(cu, a0, fmn, a2);

        // eager gate (all inputs live in regs)
        float p0 = cu * wg[0][0] + a0 * wg[1][0] + a1 * wg[2][0] + a2 * wg[3][0];
        float p1 = cu * wg[0][1] + a0 * wg[1][1] + a1 * wg[2][1] + a2 * wg[3][1];
        float p2 = cu * wg[0][2] + a0 * wg[1][2] + a1 * wg[2][2] + a2 * wg[3][2];
#pragma unroll
        for (int o = 16; o > 0; o >>= 1) {
            p0 += __shfl_xor_sync(FULL, p0, o);
            p1 += __shfl_xor_sync(FULL, p1, o);
            p2 += __shfl_xor_sync(FULL, p2, o);
        }
        if (lane == 0) {
            const float g0 = p0 + bg0, g1 = p1 + bg1, g2 = p2 + bg2;
            const float mx = fmaxf(g0, fmaxf(g1, g2));
            const float e0 = __expf(g0 - mx), e1 = __expf(g1 - mx), e2 = __expf(g2 - mx);
            const float inv = __fdividef(1.f, e0 + e1 + e2);
            gwp[c] = make_float4(e0 * inv, e1 * inv, e2 * inv, 0.f);
        }
    }
    __syncwarp();

    // ---- fused pass: loc, fun, CNF conditioning half (h2) ----
    float accL[CPW], accF[CPW], h2[CPW];
    {
        const float bl = __ldg(b_loc + lane);
        const float bf = __ldg(b_fun + lane);
        const float bc = __ldg(b_cnf + lane);
#pragma unroll
        for (int c = 0; c < CPW; c++) { accL[c] = bl; accF[c] = bf; h2[c] = bc; }
    }

#pragma unroll
    for (int i4 = 0; i4 < 8; i4++) {
        const float4 wlT = sWloc4[i4 * 32 + lane];
        const float4 wlB = sWloc4[(i4 + 8) * 32 + lane];
        const float4 wfT = sWfun4[i4 * 32 + lane];
        const float4 wfB = sWfun4[(i4 + 8) * 32 + lane];
        const float4 wcB = sWcnf4[(i4 + 8) * 32 + lane];
#pragma unroll
        for (int c = 0; c < CPW; c++) {
            const float4 x0 = inb[c * D + 4 * i4 + 0];
            const float4 x1 = inb[c * D + 4 * i4 + 1];
            const float4 x2 = inb[c * D + 4 * i4 + 2];
            const float4 x3 = inb[c * D + 4 * i4 + 3];
            accL[c] = fmaf(x0.x, wlT.x, fmaf(x0.y, wlB.x, accL[c]));
            accL[c] = fmaf(x1.x, wlT.y, fmaf(x1.y, wlB.y, accL[c]));
            accL[c] = fmaf(x2.x, wlT.z, fmaf(x2.y, wlB.z, accL[c]));
            accL[c] = fmaf(x3.x, wlT.w, fmaf(x3.y, wlB.w, accL[c]));
            accF[c] = fmaf(x0.x, wfT.x, fmaf(x0.z, wfB.x, accF[c]));
            accF[c] = fmaf(x1.x, wfT.y, fmaf(x1.z, wfB.y, accF[c]));
            accF[c] = fmaf(x2.x, wfT.z, fmaf(x2.z, wfB.z, accF[c]));
            accF[c] = fmaf(x3.x, wfT.w, fmaf(x3.z, wfB.w, accF[c]));
            h2[c]   = fmaf(x0.w, wcB.x, h2[c]);
            h2[c]   = fmaf(x1.w, wcB.y, h2[c]);
            h2[c]   = fmaf(x2.w, wcB.z, h2[c]);
            h2[c]   = fmaf(x3.w, wcB.w, h2[c]);
        }
    }

    // ---- partial combine, init CNF state ----
    float opart[CPW], gw2[CPW], x[CPW];
#pragma unroll
    for (int c = 0; c < CPW; c++) {
        const float4 gwv = gwp[c];
        opart[c] = gwv.x * tanh_fast(accL[c]) + gwv.y * tanh_fast(accF[c]);
        gw2[c]   = gwv.z;
        x[c]     = inb[c * D + lane].x;
    }
    __syncwarp();

    // ---- CNF: 3 Euler steps; x staged into the now-dead sIn region ----
    float* xxb = reinterpret_cast<float*>(inb);
#pragma unroll
    for (int s = 0; s < 3; s++) {
        __syncwarp();
#pragma unroll
        for (int c = 0; c < CPW; c++) xxb[c * XSTR + lane] = x[c];
        __syncwarp();
        float acc[CPW];
#pragma unroll
        for (int c = 0; c < CPW; c++) acc[c] = h2[c];
#pragma unroll
        for (int i4 = 0; i4 < 8; i4++) {
            const float4 w = sWcnf4[i4 * 32 + lane];
#pragma unroll
            for (int c = 0; c < CPW; c++) {
                const float4 xv = *reinterpret_cast<const float4*>(xxb + c * XSTR + 4 * i4);
                acc[c] = fmaf(xv.x, w.x, fmaf(xv.y, w.y, fmaf(xv.z, w.z, fmaf(xv.w, w.w, acc[c]))));
            }
        }
#pragma unroll
        for (int c = 0; c < CPW; c++)
            x[c] = fmaf(1.0f / 3.0f, tanh_fast(acc[c]), x[c]);
    }

    // ---- final combine + store ----
#pragma unroll
    for (int c = 0; c < CPW; c++) {
        const int cell = base + c;
        if (cell < n)
            out[cell * D + lane] = opart[c] + gw2[c] * x[c];
    }
}

extern "C" void kernel_launch(void* const* d_in, const int* in_sizes, int n_in,
                              void* d_out, int out_size) {
    const float* states = (const float*)d_in[0];
    const int*   nbr    = (const int*)  d_in[1];
    const int*   tiers  = (const int*)  d_in[2];
    const float* W_loc  = (const float*)d_in[3];
    const float* b_loc  = (const float*)d_in[4];
    const float* W_msg  = (const float*)d_in[5];
    const float* b_msg  = (const float*)d_in[6];
    const float* W_fun  = (const float*)d_in[7];
    const float* b_fun  = (const float*)d_in[8];
    const float* W_cnf  = (const float*)d_in[9];
    const float* b_cnf  = (const float*)d_in[10];
    const float* W_gate = (const float*)d_in[11];
    const float* b_gate = (const float*)d_in[12];
    float* out = (float*)d_out;

    const int n = in_sizes[0] / D;
    const int blocksP = (n + 12 * 4 - 1) / (12 * 4);
    const int blocks  = (n + WPB * CPW - 1) / (WPB * CPW);

    const int smem_bytes = (3 * 16 * 32) * (int)sizeof(float4)
                         + (WPB * CPW * D) * (int)sizeof(float4)
                         + (WPB * CPW) * (int)sizeof(float4);
    static bool attr_set = false;
    if (!attr_set) {
        cudaFuncSetAttribute(moe_main, cudaFuncAttributeMaxDynamicSharedMemorySize, smem_bytes);
        attr_set = true;
    }

    msg_prepass<<<blocksP, 384>>>(n, states, W_msg, b_msg);
    moe_main<<<blocks, TPB, smem_bytes>>>(n, states, nbr, tiers,
                                          W_loc, b_loc, W_fun, b_fun,
                                          W_cnf, b_cnf, W_gate, b_gate, out);
}

// round 15
// speedup vs baseline: 1.2230x; 1.0245x over previous
#include <cuda_runtime.h>

#define D    32
#define KN   26
#define CPW  8               // cells per warp (main + prepass)
#define WPB  12
#define TPB  (WPB * 32)
#define NMAX 125000
#define XSTR 36
#define MASK26 0x3ffffffu

__device__ float g_msg[NMAX * D];

__device__ __forceinline__ float tanh_fast(float x) {
    float y;
    asm("tanh.approx.f32 %0, %1;" : "=f"(y) : "f"(x));
    return y;
}

// ---------------------------------------------------------------------------
// Prepass: g_msg[cell] = tanh(states[cell] @ W_msg + b_msg), 8 cells/warp
// ---------------------------------------------------------------------------
__global__ __launch_bounds__(TPB) void msg_prepass(
    int n, const float* __restrict__ states,
    const float* __restrict__ W_msg, const float* __restrict__ b_msg)
{
    __shared__ float sx[WPB][CPW * XSTR];
    const int lane = threadIdx.x & 31, warp = threadIdx.x >> 5;
    const int base = (blockIdx.x * WPB + warp) * CPW;
    if (base >= n) return;

    float wm[D];                                   // lane holds W_msg[:, lane]
#pragma unroll
    for (int i = 0; i < D; i++) wm[i] = __ldg(W_msg + i * D + lane);
    const float bm = __ldg(b_msg + lane);

    float* xb = sx[warp];
#pragma unroll
    for (int c = 0; c < CPW; c++) {
        int cell = min(base + c, n - 1);
        xb[c * XSTR + lane] = states[cell * D + lane];
    }
    __syncwarp();
#pragma unroll
    for (int c = 0; c < CPW; c++) {
        int cell = base + c;
        float m = bm;
#pragma unroll
        for (int i8 = 0; i8 < 8; i8++) {
            float4 xv = *reinterpret_cast<const float4*>(xb + c * XSTR + 4 * i8);
            m = fmaf(xv.x, wm[4 * i8 + 0], m);
            m = fmaf(xv.y, wm[4 * i8 + 1], m);
            m = fmaf(xv.z, wm[4 * i8 + 2], m);
            m = fmaf(xv.w, wm[4 * i8 + 3], m);
        }
        if (cell < n) g_msg[cell * D + lane] = tanh_fast(m);
    }
}

// ---------------------------------------------------------------------------
// Main kernel: R9 structure (8 cells/warp, eager gate, sIn-reuse CNF) with
// msg address derived from state address via uniform delta (saves IMAD.WIDE)
// ---------------------------------------------------------------------------
__global__ __launch_bounds__(TPB, 3) void moe_main(
    int n,
    const float* __restrict__ states,
    const int*   __restrict__ nbr,
    const int*   __restrict__ tiers,
    const float* __restrict__ W_loc,  const float* __restrict__ b_loc,
    const float* __restrict__ W_fun,  const float* __restrict__ b_fun,
    const float* __restrict__ W_cnf,  const float* __restrict__ b_cnf,
    const float* __restrict__ W_gate, const float* __restrict__ b_gate,
    float* __restrict__ out)
{
    extern __shared__ char smem[];
    float4* sWloc4 = reinterpret_cast<float4*>(smem);
    float4* sWfun4 = sWloc4 + 16 * 32;
    float4* sWcnf4 = sWfun4 + 16 * 32;
    float4* sInAll = sWcnf4 + 16 * 32;           // WPB*CPW*32 float4
    float4* sGate  = sInAll + WPB * CPW * D;     // WPB*CPW

    for (int e = threadIdx.x; e < 16 * 32; e += TPB) {
        int i = (e >> 5) * 4, j = e & 31;
        sWloc4[e] = make_float4(W_loc[i * 32 + j], W_loc[(i + 1) * 32 + j],
                                W_loc[(i + 2) * 32 + j], W_loc[(i + 3) * 32 + j]);
        sWfun4[e] = make_float4(W_fun[i * 32 + j], W_fun[(i + 1) * 32 + j],
                                W_fun[(i + 2) * 32 + j], W_fun[(i + 3) * 32 + j]);
        sWcnf4[e] = make_float4(W_cnf[i * 32 + j], W_cnf[(i + 1) * 32 + j],
                                W_cnf[(i + 2) * 32 + j], W_cnf[(i + 3) * 32 + j]);
    }
    __syncthreads();

    const int lane = threadIdx.x & 31, warp = threadIdx.x >> 5;
    const int base = (blockIdx.x * WPB + warp) * CPW;
    if (base >= n) return;
    const unsigned FULL = 0xffffffffu;

    const char* sb = (const char*)states + lane * 4;   // lane-offset state base
    const long  msgdelta = (const char*)g_msg - (const char*)states; // uniform

    float4* inb = sInAll + warp * (CPW * D);
    float4* gwp = sGate  + warp * CPW;

    float wg[4][3];
#pragma unroll
    for (int s = 0; s < 4; s++)
#pragma unroll
        for (int e = 0; e < 3; e++)
            wg[s][e] = __ldg(W_gate + (s * D + lane) * 3 + e);
    const float bg0 = __ldg(b_gate + 0), bg1 = __ldg(b_gate + 1), bg2 = __ldg(b_gate + 2);

    const int lnk = min(lane, KN - 1);

    // ---- gather + tier means + EAGER gate ----
#pragma unroll
    for (int c = 0; c < CPW; c++) {
        const int cellc = min(base + c, n - 1);

        const float cu = states[cellc * D + lane];
        const int idx  = __ldg(nbr   + cellc * KN + lnk);
        const int myt  = __ldg(tiers + cellc * KN + lnk);
        const int mypk = idx * 128 + myt;

        const unsigned m0 = __ballot_sync(FULL, myt == 0) & MASK26;
        const unsigned m1 = __ballot_sync(FULL, myt == 1) & MASK26;
        const int n0 = __popc(m0), n1 = __popc(m1);
        const int n2 = KN - n0 - n1;

        float tot = 0.f, a0s = 0.f, s01 = 0.f, fm = 0.f;
#pragma unroll
        for (int k = 0; k < KN; k++) {
            const int pk  = __shfl_sync(FULL, mypk, k);
            const int t   = pk & 3;
            const char* sa = sb + (long)(pk & ~127);           // one 64-bit addr
            const float v = __ldcg((const float*)sa);
            float mv;                                           // msg addr = sa + delta
            asm("{.reg .pred p; setp.eq.s32 p, %2, 1; mov.f32 %0, 0f00000000;"
                " @p ld.global.cg.f32 %0, [%1];}"
                : "=f"(mv) : "l"(sa + msgdelta), "r"(t));
            tot += v;
            a0s += (t == 0) ? v : 0.f;
            s01 += (t <= 1) ? v : 0.f;
            fm  += mv;
        }

        const float a0 = __fdividef(a0s,       fmaxf((float)n0, 1.f));
        const float a1 = __fdividef(s01 - a0s, fmaxf((float)n1, 1.f));
        const float a2 = __fdividef(tot - s01, fmaxf((float)n2, 1.f));
        const float fmn = __fdividef(fm,       fmaxf((float)n1, 1.f));

        inb[c * D + lane] = make_float4(cu, a0, fmn, a2);

        // eager gate (all inputs live in regs)
        float p0 = cu * wg[0][0] + a0 * wg[1][0] + a1 * wg[2][0] + a2 * wg[3][0];
        float p1 = cu * wg[0][1] + a0 * wg[1][1] + a1 * wg[2][1] + a2 * wg[3][1];
        float p2 = cu * wg[0][2] + a0 * wg[1][2] + a1 * wg[2][2] + a2 * wg[3][2];
#pragma unroll
        for (int o = 16; o > 0; o >>= 1) {
            p0 += __shfl_xor_sync(FULL, p0, o);
            p1 += __shfl_xor_sync(FULL, p1, o);
            p2 += __shfl_xor_sync(FULL, p2, o);
        }
        if (lane == 0) {
            const float g0 = p0 + bg0, g1 = p1 + bg1, g2 = p2 + bg2;
            const float mx = fmaxf(g0, fmaxf(g1, g2));
            const float e0 = __expf(g0 - mx), e1 = __expf(g1 - mx), e2 = __expf(g2 - mx);
            const float inv = __fdividef(1.f, e0 + e1 + e2);
            gwp[c] = make_float4(e0 * inv, e1 * inv, e2 * inv, 0.f);
        }
    }
    __syncwarp();

    // ---- fused pass: loc, fun, CNF conditioning half (h2); 8-cell amortized ----
    float accL[CPW], accF[CPW], h2[CPW];
    {
        const float bl = __ldg(b_loc + lane);
        const float bf = __ldg(b_fun + lane);
        const float bc = __ldg(b_cnf + lane);
#pragma unroll
        for (int c = 0; c < CPW; c++) { accL[c] = bl; accF[c] = bf; h2[c] = bc; }
    }

#pragma unroll
    for (int i4 = 0; i4 < 8; i4++) {
        const float4 wlT = sWloc4[i4 * 32 + lane];
        const float4 wlB = sWloc4[(i4 + 8) * 32 + lane];
        const float4 wfT = sWfun4[i4 * 32 + lane];
        const float4 wfB = sWfun4[(i4 + 8) * 32 + lane];
        const float4 wcB = sWcnf4[(i4 + 8) * 32 + lane];
#pragma unroll
        for (int c = 0; c < CPW; c++) {
            const float4 x0 = inb[c * D + 4 * i4 + 0];
            const float4 x1 = inb[c * D + 4 * i4 + 1];
            const float4 x2 = inb[c * D + 4 * i4 + 2];
            const float4 x3 = inb[c * D + 4 * i4 + 3];
            accL[c] = fmaf(x0.x, wlT.x, fmaf(x0.y, wlB.x, accL[c]));
            accL[c] = fmaf(x1.x, wlT.y, fmaf(x1.y, wlB.y, accL[c]));
            accL[c] = fmaf(x2.x, wlT.z, fmaf(x2.y, wlB.z, accL[c]));
            accL[c] = fmaf(x3.x, wlT.w, fmaf(x3.y, wlB.w, accL[c]));
            accF[c] = fmaf(x0.x, wfT.x, fmaf(x0.z, wfB.x, accF[c]));
            accF[c] = fmaf(x1.x, wfT.y, fmaf(x1.z, wfB.y, accF[c]));
            accF[c] = fmaf(x2.x, wfT.z, fmaf(x2.z, wfB.z, accF[c]));
            accF[c] = fmaf(x3.x, wfT.w, fmaf(x3.z, wfB.w, accF[c]));
            h2[c]   = fmaf(x0.w, wcB.x, h2[c]);
            h2[c]   = fmaf(x1.w, wcB.y, h2[c]);
            h2[c]   = fmaf(x2.w, wcB.z, h2[c]);
            h2[c]   = fmaf(x3.w, wcB.w, h2[c]);
        }
    }

    // ---- partial combine, init CNF state ----
    float opart[CPW], gw2[CPW], x[CPW];
#pragma unroll
    for (int c = 0; c < CPW; c++) {
        const float4 gwv = gwp[c];
        opart[c] = gwv.x * tanh_fast(accL[c]) + gwv.y * tanh_fast(accF[c]);
        gw2[c]   = gwv.z;
        x[c]     = inb[c * D + lane].x;
    }
    __syncwarp();

    // ---- CNF: 3 Euler steps; x staged into the now-dead sIn region ----
    float* xxb = reinterpret_cast<float*>(inb);
#pragma unroll
    for (int s = 0; s < 3; s++) {
        __syncwarp();
#pragma unroll
        for (int c = 0; c < CPW; c++) xxb[c * XSTR + lane] = x[c];
        __syncwarp();
        float acc[CPW];
#pragma unroll
        for (int c = 0; c < CPW; c++) acc[c] = h2[c];
#pragma unroll
        for (int i4 = 0; i4 < 8; i4++) {
            const float4 w = sWcnf4[i4 * 32 + lane];
#pragma unroll
            for (int c = 0; c < CPW; c++) {
                const float4 xv = *reinterpret_cast<const float4*>(xxb + c * XSTR + 4 * i4);
                acc[c] = fmaf(xv.x, w.x, fmaf(xv.y, w.y, fmaf(xv.z, w.z, fmaf(xv.w, w.w, acc[c]))));
            }
        }
#pragma unroll
        for (int c = 0; c < CPW; c++)
            x[c] = fmaf(1.0f / 3.0f, tanh_fast(acc[c]), x[c]);
    }

    // ---- final combine + store ----
#pragma unroll
    for (int c = 0; c < CPW; c++) {
        const int cell = base + c;
        if (cell < n)
            out[cell * D + lane] = opart[c] + gw2[c] * x[c];
    }
}

extern "C" void kernel_launch(void* const* d_in, const int* in_sizes, int n_in,
                              void* d_out, int out_size) {
    const float* states = (const float*)d_in[0];
    const int*   nbr    = (const int*)  d_in[1];
    const int*   tiers  = (const int*)  d_in[2];
    const float* W_loc  = (const float*)d_in[3];
    const float* b_loc  = (const float*)d_in[4];
    const float* W_msg  = (const float*)d_in[5];
    const float* b_msg  = (const float*)d_in[6];
    const float* W_fun  = (const float*)d_in[7];
    const float* b_fun  = (const float*)d_in[8];
    const float* W_cnf  = (const float*)d_in[9];
    const float* b_cnf  = (const float*)d_in[10];
    const float* W_gate = (const float*)d_in[11];
    const float* b_gate = (const float*)d_in[12];
    float* out = (float*)d_out;

    const int n = in_sizes[0] / D;
    const int blocks = (n + WPB * CPW - 1) / (WPB * CPW);

    // smem: weights 24 KB + sIn 48 KB + sGate 1.5 KB
    const int smem_bytes = (3 * 16 * 32) * (int)sizeof(float4)
                         + (WPB * CPW * D) * (int)sizeof(float4)
                         + (WPB * CPW) * (int)sizeof(float4);
    static bool attr_set = false;
    if (!attr_set) {
        cudaFuncSetAttribute(moe_main, cudaFuncAttributeMaxDynamicSharedMemorySize, smem_bytes);
        attr_set = true;
    }

    msg_prepass<<<blocks, TPB>>>(n, states, W_msg, b_msg);
    moe_main<<<blocks, TPB, smem_bytes>>>(n, states, nbr, tiers,
                                          W_loc, b_loc, W_fun, b_fun,
                                          W_cnf, b_cnf, W_gate, b_gate, out);
}

// round 16
// speedup vs baseline: 1.2396x; 1.0136x over previous
#include <cuda_runtime.h>

#define D    32
#define KN   26
#define CPW  8               // cells per warp (main + prepass)
#define WPB  12
#define TPB  (WPB * 32)
#define NMAX 125000
#define XSTR 36

__device__ float g_msg[NMAX * D];

__device__ __forceinline__ float tanh_fast(float x) {
    float y;
    asm("tanh.approx.f32 %0, %1;" : "=f"(y) : "f"(x));
    return y;
}

// ---------------------------------------------------------------------------
// Prepass (R15, measured 7.2us): g_msg = tanh(states @ W_msg + b), 8 cells/warp
// ---------------------------------------------------------------------------
__global__ __launch_bounds__(TPB) void msg_prepass(
    int n, const float* __restrict__ states,
    const float* __restrict__ W_msg, const float* __restrict__ b_msg)
{
    __shared__ float sx[WPB][CPW * XSTR];
    const int lane = threadIdx.x & 31, warp = threadIdx.x >> 5;
    const int base = (blockIdx.x * WPB + warp) * CPW;
    if (base >= n) return;

    float wm[D];                                   // lane holds W_msg[:, lane]
#pragma unroll
    for (int i = 0; i < D; i++) wm[i] = __ldg(W_msg + i * D + lane);
    const float bm = __ldg(b_msg + lane);

    float* xb = sx[warp];
#pragma unroll
    for (int c = 0; c < CPW; c++) {
        int cell = min(base + c, n - 1);
        xb[c * XSTR + lane] = states[cell * D + lane];
    }
    __syncwarp();
#pragma unroll
    for (int c = 0; c < CPW; c++) {
        int cell = base + c;
        float m = bm;
#pragma unroll
        for (int i8 = 0; i8 < 8; i8++) {
            float4 xv = *reinterpret_cast<const float4*>(xb + c * XSTR + 4 * i8);
            m = fmaf(xv.x, wm[4 * i8 + 0], m);
            m = fmaf(xv.y, wm[4 * i8 + 1], m);
            m = fmaf(xv.z, wm[4 * i8 + 2], m);
            m = fmaf(xv.w, wm[4 * i8 + 3], m);
        }
        if (cell < n) g_msg[cell * D + lane] = tanh_fast(m);
    }
}

// ---------------------------------------------------------------------------
// Main kernel (R9 verbatim, measured 178.3us): 8 cells/warp, eager gate,
// sIn-reuse CNF staging
// ---------------------------------------------------------------------------
__global__ __launch_bounds__(TPB, 3) void moe_main(
    int n,
    const float* __restrict__ states,
    const int*   __restrict__ nbr,
    const int*   __restrict__ tiers,
    const float* __restrict__ W_loc,  const float* __restrict__ b_loc,
    const float* __restrict__ W_fun,  const float* __restrict__ b_fun,
    const float* __restrict__ W_cnf,  const float* __restrict__ b_cnf,
    const float* __restrict__ W_gate, const float* __restrict__ b_gate,
    float* __restrict__ out)
{
    extern __shared__ char smem[];
    float4* sWloc4 = reinterpret_cast<float4*>(smem);                 // 16*32
    float4* sWfun4 = sWloc4 + 16 * 32;
    float4* sWcnf4 = sWfun4 + 16 * 32;
    float4* sInAll = sWcnf4 + 16 * 32;                                // WPB*CPW*32 float4
    float4* sGate  = sInAll + WPB * CPW * D;                          // WPB*CPW

    for (int e = threadIdx.x; e < 16 * 32; e += TPB) {
        int i = (e >> 5) * 4, j = e & 31;
        sWloc4[e] = make_float4(W_loc[i * 32 + j], W_loc[(i + 1) * 32 + j],
                                W_loc[(i + 2) * 32 + j], W_loc[(i + 3) * 32 + j]);
        sWfun4[e] = make_float4(W_fun[i * 32 + j], W_fun[(i + 1) * 32 + j],
                                W_fun[(i + 2) * 32 + j], W_fun[(i + 3) * 32 + j]);
        sWcnf4[e] = make_float4(W_cnf[i * 32 + j], W_cnf[(i + 1) * 32 + j],
                                W_cnf[(i + 2) * 32 + j], W_cnf[(i + 3) * 32 + j]);
    }
    __syncthreads();

    const int lane = threadIdx.x & 31, warp = threadIdx.x >> 5;
    const int base = (blockIdx.x * WPB + warp) * CPW;
    if (base >= n) return;
    const unsigned FULL = 0xffffffffu;

    const char* sb = (const char*)states + lane * 4;
    const char* mb = (const char*)g_msg  + lane * 4;

    float4* inb = sInAll + warp * (CPW * D);
    float4* gwp = sGate  + warp * CPW;

    // gate params (used inside gather loop)
    float wg[4][3];
#pragma unroll
    for (int s = 0; s < 4; s++)
#pragma unroll
        for (int e = 0; e < 3; e++)
            wg[s][e] = __ldg(W_gate + (s * D + lane) * 3 + e);
    const float bg0 = __ldg(b_gate + 0), bg1 = __ldg(b_gate + 1), bg2 = __ldg(b_gate + 2);

    // ---- gather + tier means + EAGER gate (all inputs live in regs here) ----
#pragma unroll
    for (int c = 0; c < CPW; c++) {
        const int cell = base + c;
        const bool act = (cell < n);

        float cu = act ? states[cell * D + lane] : 0.f;
        int mypk = 3, myt = 3;
        if (act && lane < KN) {
            int idx = __ldg(nbr   + cell * KN + lane);
            myt     = __ldg(tiers + cell * KN + lane);
            mypk    = idx * 128 + myt;
        }
        const unsigned mask0 = __ballot_sync(FULL, myt == 0);
        const unsigned mask1 = __ballot_sync(FULL, myt == 1);
        const float n0 = (float)__popc(mask0);
        const float n1 = (float)__popc(mask1);
        const float n2 = act ? (float)(KN) - n0 - n1 : 0.f;

        float a0 = 0.f, a1 = 0.f, tot = 0.f, fm = 0.f;
#pragma unroll
        for (int k = 0; k < KN; k++) {
            const int pk  = __shfl_sync(FULL, mypk, k);
            const int t   = pk & 3;
            const long off = (long)(pk & ~127);
            const float v = __ldcg((const float*)(sb + off));
            float mv;
            asm("{ .reg .pred p;\n\t"
                "  setp.eq.s32 p, %1, 1;\n\t"
                "  mov.f32 %0, 0f00000000;\n\t"
                "  @p ld.global.cg.f32 %0, [%2];\n\t"
                "}" : "=f"(mv) : "r"(t), "l"(mb + off));
            tot += v;
            a0  += (t == 0) ? v : 0.f;
            a1  += (t == 1) ? v : 0.f;
            fm  += mv;
        }
        float a2 = tot - a0 - a1;

        a0 = __fdividef(a0, fmaxf(n0, 1.f));
        a1 = __fdividef(a1, fmaxf(n1, 1.f));
        a2 = __fdividef(a2, fmaxf(n2, 1.f));
        fm = __fdividef(fm, fmaxf(n1, 1.f));

        inb[c * D + lane] = make_float4(cu, a0, fm, a2);

        // gate: softmax([cur;a0;a1;a2] @ W_gate + b) -- all inputs in regs
        float p0 = cu * wg[0][0] + a0 * wg[1][0] + a1 * wg[2][0] + a2 * wg[3][0];
        float p1 = cu * wg[0][1] + a0 * wg[1][1] + a1 * wg[2][1] + a2 * wg[3][1];
        float p2 = cu * wg[0][2] + a0 * wg[1][2] + a1 * wg[2][2] + a2 * wg[3][2];
#pragma unroll
        for (int o = 16; o > 0; o >>= 1) {
            p0 += __shfl_xor_sync(FULL, p0, o);
            p1 += __shfl_xor_sync(FULL, p1, o);
            p2 += __shfl_xor_sync(FULL, p2, o);
        }
        if (lane == 0) {
            const float g0 = p0 + bg0, g1 = p1 + bg1, g2 = p2 + bg2;
            const float mx = fmaxf(g0, fmaxf(g1, g2));
            const float e0 = __expf(g0 - mx), e1 = __expf(g1 - mx), e2 = __expf(g2 - mx);
            const float inv = __fdividef(1.f, e0 + e1 + e2);
            gwp[c] = make_float4(e0 * inv, e1 * inv, e2 * inv, 0.f);
        }
    }
    __syncwarp();

    // ---- fused pass: loc, fun, CNF cond half; weights amortized over 8 cells ----
    float accL[CPW], accF[CPW], h2[CPW];
    {
        const float bl = __ldg(b_loc + lane);
        const float bf = __ldg(b_fun + lane);
        const float bc = __ldg(b_cnf + lane);
#pragma unroll
        for (int c = 0; c < CPW; c++) { accL[c] = bl; accF[c] = bf; h2[c] = bc; }
    }

#pragma unroll
    for (int i4 = 0; i4 < 8; i4++) {
        const float4 wlT = sWloc4[i4 * 32 + lane];
        const float4 wlB = sWloc4[(i4 + 8) * 32 + lane];
        const float4 wfT = sWfun4[i4 * 32 + lane];
        const float4 wfB = sWfun4[(i4 + 8) * 32 + lane];
        const float4 wcB = sWcnf4[(i4 + 8) * 32 + lane];
#pragma unroll
        for (int c = 0; c < CPW; c++) {
            const float4 x0 = inb[c * D + 4 * i4 + 0];
            const float4 x1 = inb[c * D + 4 * i4 + 1];
            const float4 x2 = inb[c * D + 4 * i4 + 2];
            const float4 x3 = inb[c * D + 4 * i4 + 3];
            accL[c] = fmaf(x0.x, wlT.x, fmaf(x0.y, wlB.x, accL[c]));
            accL[c] = fmaf(x1.x, wlT.y, fmaf(x1.y, wlB.y, accL[c]));
            accL[c] = fmaf(x2.x, wlT.z, fmaf(x2.y, wlB.z, accL[c]));
            accL[c] = fmaf(x3.x, wlT.w, fmaf(x3.y, wlB.w, accL[c]));
            accF[c] = fmaf(x0.x, wfT.x, fmaf(x0.z, wfB.x, accF[c]));
            accF[c] = fmaf(x1.x, wfT.y, fmaf(x1.z, wfB.y, accF[c]));
            accF[c] = fmaf(x2.x, wfT.z, fmaf(x2.z, wfB.z, accF[c]));
            accF[c] = fmaf(x3.x, wfT.w, fmaf(x3.z, wfB.w, accF[c]));
            h2[c]   = fmaf(x0.w, wcB.x, h2[c]);
            h2[c]   = fmaf(x1.w, wcB.y, h2[c]);
            h2[c]   = fmaf(x2.w, wcB.z, h2[c]);
            h2[c]   = fmaf(x3.w, wcB.w, h2[c]);
        }
    }

    // ---- partial combine (frees accL/accF), init CNF state ----
    float opart[CPW], gw2[CPW], x[CPW];
#pragma unroll
    for (int c = 0; c < CPW; c++) {
        const float4 gwv = gwp[c];                       // uniform LDS.128
        opart[c] = gwv.x * tanh_fast(accL[c]) + gwv.y * tanh_fast(accF[c]);
        gw2[c]   = gwv.z;
        x[c]     = inb[c * D + lane].x;                  // cur
    }
    __syncwarp();

    // ---- CNF: 3 Euler steps; x staged into the now-dead sIn region ----
    float* xxb = reinterpret_cast<float*>(inb);          // reuse: all sIn dead
#pragma unroll
    for (int s = 0; s < 3; s++) {
        __syncwarp();
#pragma unroll
        for (int c = 0; c < CPW; c++) xxb[c * XSTR + lane] = x[c];
        __syncwarp();
        float acc[CPW];
#pragma unroll
        for (int c = 0; c < CPW; c++) acc[c] = h2[c];
#pragma unroll
        for (int i4 = 0; i4 < 8; i4++) {
            const float4 w = sWcnf4[i4 * 32 + lane];
#pragma unroll
            for (int c = 0; c < CPW; c++) {
                const float4 xv = *reinterpret_cast<const float4*>(xxb + c * XSTR + 4 * i4);
                acc[c] = fmaf(xv.x, w.x, fmaf(xv.y, w.y, fmaf(xv.z, w.z, fmaf(xv.w, w.w, acc[c]))));
            }
        }
#pragma unroll
        for (int c = 0; c < CPW; c++)
            x[c] = fmaf(1.0f / 3.0f, tanh_fast(acc[c]), x[c]);
    }

    // ---- final combine + store ----
#pragma unroll
    for (int c = 0; c < CPW; c++) {
        const int cell = base + c;
        if (cell < n)
            out[cell * D + lane] = opart[c] + gw2[c] * x[c];
    }
}

extern "C" void kernel_launch(void* const* d_in, const int* in_sizes, int n_in,
                              void* d_out, int out_size) {
    const float* states = (const float*)d_in[0];
    const int*   nbr    = (const int*)  d_in[1];
    const int*   tiers  = (const int*)  d_in[2];
    const float* W_loc  = (const float*)d_in[3];
    const float* b_loc  = (const float*)d_in[4];
    const float* W_msg  = (const float*)d_in[5];
    const float* b_msg  = (const float*)d_in[6];
    const float* W_fun  = (const float*)d_in[7];
    const float* b_fun  = (const float*)d_in[8];
    const float* W_cnf  = (const float*)d_in[9];
    const float* b_cnf  = (const float*)d_in[10];
    const float* W_gate = (const float*)d_in[11];
    const float* b_gate = (const float*)d_in[12];
    float* out = (float*)d_out;

    const int n = in_sizes[0] / D;
    const int blocks = (n + WPB * CPW - 1) / (WPB * CPW);

    // smem: weights 24 KB + sIn 48 KB + sGate 1.5 KB = 73.5 KB -> 3 blocks/SM
    const int smem_bytes = (3 * 16 * 32) * (int)sizeof(float4)
                         + (WPB * CPW * D) * (int)sizeof(float4)
                         + (WPB * CPW) * (int)sizeof(float4);
    static bool attr_set = false;
    if (!attr_set) {
        cudaFuncSetAttribute(moe_main, cudaFuncAttributeMaxDynamicSharedMemorySize, smem_bytes);
        attr_set = true;
    }

    msg_prepass<<<blocks, TPB>>>(n, states, W_msg, b_msg);
    moe_main<<<blocks, TPB, smem_bytes>>>(n, states, nbr, tiers,
                                          W_loc, b_loc, W_fun, b_fun,
                                          W_cnf, b_cnf, W_gate, b_gate, out);
}

// round 17
// speedup vs baseline: 1.2753x; 1.0288x over previous
#include <cuda_runtime.h>
#include <cuda_fp16.h>

#define D    32
#define KN   26
#define CPW  8               // cells per warp (main + prepass)
#define WPB  12
#define TPB  (WPB * 32)
#define NMAX 125000
#define XSTR 36

// combined table: half2 {state, msg} per (cell, dim); row stride = 128 B
__device__ unsigned g_pair[NMAX * D];

__device__ __forceinline__ float tanh_fast(float x) {
    float y;
    asm("tanh.approx.f32 %0, %1;" : "=f"(y) : "f"(x));
    return y;
}

// ---------------------------------------------------------------------------
// Prepass: g_pair[cell][lane] = half2(state, tanh(state @ W_msg + b_msg))
// ---------------------------------------------------------------------------
__global__ __launch_bounds__(TPB) void msg_prepass(
    int n, const float* __restrict__ states,
    const float* __restrict__ W_msg, const float* __restrict__ b_msg)
{
    __shared__ float sx[WPB][CPW * XSTR];
    const int lane = threadIdx.x & 31, warp = threadIdx.x >> 5;
    const int base = (blockIdx.x * WPB + warp) * CPW;
    if (base >= n) return;

    float wm[D];                                   // lane holds W_msg[:, lane]
#pragma unroll
    for (int i = 0; i < D; i++) wm[i] = __ldg(W_msg + i * D + lane);
    const float bm = __ldg(b_msg + lane);

    float* xb = sx[warp];
#pragma unroll
    for (int c = 0; c < CPW; c++) {
        int cell = min(base + c, n - 1);
        xb[c * XSTR + lane] = states[cell * D + lane];
    }
    __syncwarp();
#pragma unroll
    for (int c = 0; c < CPW; c++) {
        int cell = base + c;
        float m = bm;
#pragma unroll
        for (int i8 = 0; i8 < 8; i8++) {
            float4 xv = *reinterpret_cast<const float4*>(xb + c * XSTR + 4 * i8);
            m = fmaf(xv.x, wm[4 * i8 + 0], m);
            m = fmaf(xv.y, wm[4 * i8 + 1], m);
            m = fmaf(xv.z, wm[4 * i8 + 2], m);
            m = fmaf(xv.w, wm[4 * i8 + 3], m);
        }
        if (cell < n) {
            const float st = xb[c * XSTR + lane];  // this lane's own dim value
            __half2 h = __floats2half2_rn(st, tanh_fast(m));
            g_pair[cell * D + lane] = *reinterpret_cast<unsigned*>(&h);
        }
    }
}

// ---------------------------------------------------------------------------
// Main kernel: R16 structure; gather via single fp16x2 load per neighbor
// ---------------------------------------------------------------------------
__global__ __launch_bounds__(TPB, 3) void moe_main(
    int n,
    const float* __restrict__ states,
    const int*   __restrict__ nbr,
    const int*   __restrict__ tiers,
    const float* __restrict__ W_loc,  const float* __restrict__ b_loc,
    const float* __restrict__ W_fun,  const float* __restrict__ b_fun,
    const float* __restrict__ W_cnf,  const float* __restrict__ b_cnf,
    const float* __restrict__ W_gate, const float* __restrict__ b_gate,
    float* __restrict__ out)
{
    extern __shared__ char smem[];
    float4* sWloc4 = reinterpret_cast<float4*>(smem);                 // 16*32
    float4* sWfun4 = sWloc4 + 16 * 32;
    float4* sWcnf4 = sWfun4 + 16 * 32;
    float4* sInAll = sWcnf4 + 16 * 32;                                // WPB*CPW*32 float4
    float4* sGate  = sInAll + WPB * CPW * D;                          // WPB*CPW

    for (int e = threadIdx.x; e < 16 * 32; e += TPB) {
        int i = (e >> 5) * 4, j = e & 31;
        sWloc4[e] = make_float4(W_loc[i * 32 + j], W_loc[(i + 1) * 32 + j],
                                W_loc[(i + 2) * 32 + j], W_loc[(i + 3) * 32 + j]);
        sWfun4[e] = make_float4(W_fun[i * 32 + j], W_fun[(i + 1) * 32 + j],
                                W_fun[(i + 2) * 32 + j], W_fun[(i + 3) * 32 + j]);
        sWcnf4[e] = make_float4(W_cnf[i * 32 + j], W_cnf[(i + 1) * 32 + j],
                                W_cnf[(i + 2) * 32 + j], W_cnf[(i + 3) * 32 + j]);
    }
    __syncthreads();

    const int lane = threadIdx.x & 31, warp = threadIdx.x >> 5;
    const int base = (blockIdx.x * WPB + warp) * CPW;
    if (base >= n) return;
    const unsigned FULL = 0xffffffffu;

    const char* pb = (const char*)g_pair + lane * 4;   // lane-offset pair base

    float4* inb = sInAll + warp * (CPW * D);
    float4* gwp = sGate  + warp * CPW;

    // gate params (used inside gather loop)
    float wg[4][3];
#pragma unroll
    for (int s = 0; s < 4; s++)
#pragma unroll
        for (int e = 0; e < 3; e++)
            wg[s][e] = __ldg(W_gate + (s * D + lane) * 3 + e);
    const float bg0 = __ldg(b_gate + 0), bg1 = __ldg(b_gate + 1), bg2 = __ldg(b_gate + 2);

    // ---- gather + tier means + EAGER gate ----
#pragma unroll
    for (int c = 0; c < CPW; c++) {
        const int cell = base + c;
        const bool act = (cell < n);

        float cu = act ? states[cell * D + lane] : 0.f;   // own state: exact fp32
        int mypk = 3, myt = 3;
        if (act && lane < KN) {
            int idx = __ldg(nbr   + cell * KN + lane);
            myt     = __ldg(tiers + cell * KN + lane);
            mypk    = idx * 128 + myt;                    // 128 B row stride
        }
        const unsigned mask0 = __ballot_sync(FULL, myt == 0);
        const unsigned mask1 = __ballot_sync(FULL, myt == 1);
        const float n0 = (float)__popc(mask0);
        const float n1 = (float)__popc(mask1);
        const float n2 = act ? (float)(KN) - n0 - n1 : 0.f;

        float a0 = 0.f, a1 = 0.f, tot = 0.f, fm = 0.f;
#pragma unroll
        for (int k = 0; k < KN; k++) {
            const int pk  = __shfl_sync(FULL, mypk, k);
            const int t   = pk & 3;
            const long off = (long)(pk & ~127);
            const unsigned u = __ldcg((const unsigned*)(pb + off));   // ONE load
            const float2 v2 = __half22float2(*reinterpret_cast<const __half2*>(&u));
            tot += v2.x;
            a0  += (t == 0) ? v2.x : 0.f;
            a1  += (t == 1) ? v2.x : 0.f;
            fm  += (t == 1) ? v2.y : 0.f;
        }
        float a2 = tot - a0 - a1;

        a0 = __fdividef(a0, fmaxf(n0, 1.f));
        a1 = __fdividef(a1, fmaxf(n1, 1.f));
        a2 = __fdividef(a2, fmaxf(n2, 1.f));
        fm = __fdividef(fm, fmaxf(n1, 1.f));

        inb[c * D + lane] = make_float4(cu, a0, fm, a2);

        // gate: softmax([cur;a0;a1;a2] @ W_gate + b) -- all inputs in regs
        float p0 = cu * wg[0][0] + a0 * wg[1][0] + a1 * wg[2][0] + a2 * wg[3][0];
        float p1 = cu * wg[0][1] + a0 * wg[1][1] + a1 * wg[2][1] + a2 * wg[3][1];
        float p2 = cu * wg[0][2] + a0 * wg[1][2] + a1 * wg[2][2] + a2 * wg[3][2];
#pragma unroll
        for (int o = 16; o > 0; o >>= 1) {
            p0 += __shfl_xor_sync(FULL, p0, o);
            p1 += __shfl_xor_sync(FULL, p1, o);
            p2 += __shfl_xor_sync(FULL, p2, o);
        }
        if (lane == 0) {
            const float g0 = p0 + bg0, g1 = p1 + bg1, g2 = p2 + bg2;
            const float mx = fmaxf(g0, fmaxf(g1, g2));
            const float e0 = __expf(g0 - mx), e1 = __expf(g1 - mx), e2 = __expf(g2 - mx);
            const float inv = __fdividef(1.f, e0 + e1 + e2);
            gwp[c] = make_float4(e0 * inv, e1 * inv, e2 * inv, 0.f);
        }
    }
    __syncwarp();

    // ---- fused pass: loc, fun, CNF cond half; weights amortized over 8 cells ----
    float accL[CPW], accF[CPW], h2[CPW];
    {
        const float bl = __ldg(b_loc + lane);
        const float bf = __ldg(b_fun + lane);
        const float bc = __ldg(b_cnf + lane);
#pragma unroll
        for (int c = 0; c < CPW; c++) { accL[c] = bl; accF[c] = bf; h2[c] = bc; }
    }

#pragma unroll
    for (int i4 = 0; i4 < 8; i4++) {
        const float4 wlT = sWloc4[i4 * 32 + lane];
        const float4 wlB = sWloc4[(i4 + 8) * 32 + lane];
        const float4 wfT = sWfun4[i4 * 32 + lane];
        const float4 wfB = sWfun4[(i4 + 8) * 32 + lane];
        const float4 wcB = sWcnf4[(i4 + 8) * 32 + lane];
#pragma unroll
        for (int c = 0; c < CPW; c++) {
            const float4 x0 = inb[c * D + 4 * i4 + 0];
            const float4 x1 = inb[c * D + 4 * i4 + 1];
            const float4 x2 = inb[c * D + 4 * i4 + 2];
            const float4 x3 = inb[c * D + 4 * i4 + 3];
            accL[c] = fmaf(x0.x, wlT.x, fmaf(x0.y, wlB.x, accL[c]));
            accL[c] = fmaf(x1.x, wlT.y, fmaf(x1.y, wlB.y, accL[c]));
            accL[c] = fmaf(x2.x, wlT.z, fmaf(x2.y, wlB.z, accL[c]));
            accL[c] = fmaf(x3.x, wlT.w, fmaf(x3.y, wlB.w, accL[c]));
            accF[c] = fmaf(x0.x, wfT.x, fmaf(x0.z, wfB.x, accF[c]));
            accF[c] = fmaf(x1.x, wfT.y, fmaf(x1.z, wfB.y, accF[c]));
            accF[c] = fmaf(x2.x, wfT.z, fmaf(x2.z, wfB.z, accF[c]));
            accF[c] = fmaf(x3.x, wfT.w, fmaf(x3.z, wfB.w, accF[c]));
            h2[c]   = fmaf(x0.w, wcB.x, h2[c]);
            h2[c]   = fmaf(x1.w, wcB.y, h2[c]);
            h2[c]   = fmaf(x2.w, wcB.z, h2[c]);
            h2[c]   = fmaf(x3.w, wcB.w, h2[c]);
        }
    }

    // ---- partial combine (frees accL/accF), init CNF state ----
    float opart[CPW], gw2[CPW], x[CPW];
#pragma unroll
    for (int c = 0; c < CPW; c++) {
        const float4 gwv = gwp[c];                       // uniform LDS.128
        opart[c] = gwv.x * tanh_fast(accL[c]) + gwv.y * tanh_fast(accF[c]);
        gw2[c]   = gwv.z;
        x[c]     = inb[c * D + lane].x;                  // cur (fp32 exact)
    }
    __syncwarp();

    // ---- CNF: 3 Euler steps; x staged into the now-dead sIn region ----
    float* xxb = reinterpret_cast<float*>(inb);          // reuse: all sIn dead
#pragma unroll
    for (int s = 0; s < 3; s++) {
        __syncwarp();
#pragma unroll
        for (int c = 0; c < CPW; c++) xxb[c * XSTR + lane] = x[c];
        __syncwarp();
        float acc[CPW];
#pragma unroll
        for (int c = 0; c < CPW; c++) acc[c] = h2[c];
#pragma unroll
        for (int i4 = 0; i4 < 8; i4++) {
            const float4 w = sWcnf4[i4 * 32 + lane];
#pragma unroll
            for (int c = 0; c < CPW; c++) {
                const float4 xv = *reinterpret_cast<const float4*>(xxb + c * XSTR + 4 * i4);
                acc[c] = fmaf(xv.x, w.x, fmaf(xv.y, w.y, fmaf(xv.z, w.z, fmaf(xv.w, w.w, acc[c]))));
            }
        }
#pragma unroll
        for (int c = 0; c < CPW; c++)
            x[c] = fmaf(1.0f / 3.0f, tanh_fast(acc[c]), x[c]);
    }

    // ---- final combine + store ----
#pragma unroll
    for (int c = 0; c < CPW; c++) {
        const int cell = base + c;
        if (cell < n)
            out[cell * D + lane] = opart[c] + gw2[c] * x[c];
    }
}

extern "C" void kernel_launch(void* const* d_in, const int* in_sizes, int n_in,
                              void* d_out, int out_size) {
    const float* states = (const float*)d_in[0];
    const int*   nbr    = (const int*)  d_in[1];
    const int*   tiers  = (const int*)  d_in[2];
    const float* W_loc  = (const float*)d_in[3];
    const float* b_loc  = (const float*)d_in[4];
    const float* W_msg  = (const float*)d_in[5];
    const float* b_msg  = (const float*)d_in[6];
    const float* W_fun  = (const float*)d_in[7];
    const float* b_fun  = (const float*)d_in[8];
    const float* W_cnf  = (const float*)d_in[9];
    const float* b_cnf  = (const float*)d_in[10];
    const float* W_gate = (const float*)d_in[11];
    const float* b_gate = (const float*)d_in[12];
    float* out = (float*)d_out;

    const int n = in_sizes[0] / D;
    const int blocks = (n + WPB * CPW - 1) / (WPB * CPW);

    // smem: weights 24 KB + sIn 48 KB + sGate 1.5 KB = 73.5 KB -> 3 blocks/SM
    const int smem_bytes = (3 * 16 * 32) * (int)sizeof(float4)
                         + (WPB * CPW * D) * (int)sizeof(float4)
                         + (WPB * CPW) * (int)sizeof(float4);
    static bool attr_set = false;
    if (!attr_set) {
        cudaFuncSetAttribute(moe_main, cudaFuncAttributeMaxDynamicSharedMemorySize, smem_bytes);
        attr_set = true;
    }

    msg_prepass<<<blocks, TPB>>>(n, states, W_msg, b_msg);
    moe_main<<<blocks, TPB, smem_bytes>>>(n, states, nbr, tiers,
                                          W_loc, b_loc, W_fun, b_fun,
                                          W_cnf, b_cnf, W_gate, b_gate, out);
}